// round 14
// baseline (speedup 1.0000x reference)
#include <cuda_runtime.h>

#define B_   2
#define NT_  1024
#define ND_  512
#define NH_  196
#define HP_  256      // padded hidden dim (zeros for h >= 196)
#define KL_  128
#define ROWS2_ 4

// scratch (device globals: allocation-free)
__device__ float g_wj[B_ * 8 * HP_];
__device__ float g_wc[B_ * 10 * HP_];
__device__ float g_hm[B_ * NT_ * NH_];

typedef unsigned long long u64t;

__device__ __forceinline__ u64t pack2(float x, float y) {
    u64t r; asm("mov.b64 %0, {%1, %2};" : "=l"(r) : "f"(x), "f"(y)); return r;
}
__device__ __forceinline__ float2 unpack2(u64t v) {
    float2 r; asm("mov.b64 {%0, %1}, %2;" : "=f"(r.x), "=f"(r.y) : "l"(v)); return r;
}
__device__ __forceinline__ u64t ffma2(u64t a, u64t b, u64t c) {
    u64t d; asm("fma.rn.f32x2 %0, %1, %2, %3;" : "=l"(d) : "l"(a), "l"(b), "l"(c)); return d;
}
__device__ __forceinline__ u64t add2(u64t a, u64t b) {
    u64t d; asm("add.rn.f32x2 %0, %1, %2;" : "=l"(d) : "l"(a), "l"(b)); return d;
}

// ---------------------------------------------------------------------------
// Kernel 1: fold basis into W0 rows (tiny)  [verbatim]
// ---------------------------------------------------------------------------
__global__ void precomp_kernel(const float* __restrict__ W0,
                               const float* __restrict__ b0,
                               const float* __restrict__ basis) {
    int b = blockIdx.x, h = threadIdx.x;
    float* wj = g_wj + b * 8 * HP_;
    float* wc = g_wc + b * 10 * HP_;
    if (h >= NH_) {
        for (int r = 0; r < 8;  r++) wj[r * HP_ + h] = 0.f;
        for (int r = 0; r < 10; r++) wc[r * HP_ + h] = 0.f;
        return;
    }
    const float* bs = basis + b * 6 * 3;
    wj[0 * HP_ + h] = W0[15 * NH_ + h];
    wj[4 * HP_ + h] = W0[22 * NH_ + h];
    wc[0 * HP_ + h] = W0[0 * NH_ + h];
    wc[1 * HP_ + h] = W0[1 * NH_ + h];
    wc[5 * HP_ + h] = W0[8 * NH_ + h];
    wc[9 * HP_ + h] = b0[h];
    for (int d = 0; d < 3; d++) {
        float m0x = 0.f, m0v = 0.f, m1 = 0.f, m2 = 0.f;
        for (int k = 0; k < 6; k++) {
            float bb = bs[k * 3 + d];
            m0x += bb * W0[(2  + k) * NH_ + h];
            m0v += bb * W0[(9  + k) * NH_ + h];
            m1  += bb * W0[(16 + k) * NH_ + h];
            m2  += bb * W0[(23 + k) * NH_ + h];
        }
        wj[(1 + d) * HP_ + h] = m1;
        wj[(5 + d) * HP_ + h] = m2;
        wc[(2 + d) * HP_ + h] = m0x;
        wc[(6 + d) * HP_ + h] = m0v;
    }
}

// ---------------------------------------------------------------------------
// Kernel 2: R13 main with ONE change — the light warp (1-h loop) rotates by
// CTA: role = (w - (blk & 3)) & 3; h assignment follows the role so role 3's
// h1 range [224,256) is always the all-padding one. Balances SMSP load.
// ---------------------------------------------------------------------------
__global__ __launch_bounds__(128) void main_kernel(
    const float* __restrict__ x0g, const float* __restrict__ xg,
    const float* __restrict__ Ng,  const float* __restrict__ vg) {
    __shared__ float4 ftr4[8 * 128];
    float* ftr = (float*)ftr4;
    __shared__ float red[32];

    int t = threadIdx.x;
    int blk = blockIdx.x;
    int b = blk >> 10, i = blk & (NT_ - 1);
    int lane = t & 31, w = t >> 5;
    int base = (b * NT_ + i) * ND_ * 3;

    // role-rotated h assignment (ONLY change vs R13)
    int role = (w - (blk & 3)) & 3;
    int h0  = role * 32 + lane;
    int h1i = h0 + 128;

    // --- phase 1: vbulk ---
    float vxr[4], vyr[4], vzr[4];
    float s0 = 0.f, s1 = 0.f, s2 = 0.f;
#pragma unroll
    for (int r = 0; r < 4; r++) {
        int j = t + r * 128;
        const float* vp = vg + base + j * 3;
        float a = vp[0], bb = vp[1], c = vp[2];
        vxr[r] = a; vyr[r] = bb; vzr[r] = c;
        s0 += a; s1 += bb; s2 += c;
    }
#pragma unroll
    for (int off = 16; off; off >>= 1) {
        s0 += __shfl_xor_sync(0xffffffffu, s0, off);
        s1 += __shfl_xor_sync(0xffffffffu, s1, off);
        s2 += __shfl_xor_sync(0xffffffffu, s2, off);
    }
    if (lane == 0) { red[w * 8 + 0] = s0; red[w * 8 + 1] = s1; red[w * 8 + 2] = s2; }
    __syncthreads();
    float vb0 = (red[0] + red[8]  + red[16] + red[24]) * (1.f / ND_);
    float vb1 = (red[1] + red[9]  + red[17] + red[25]) * (1.f / ND_);
    float vb2 = (red[2] + red[10] + red[18] + red[26]) * (1.f / ND_);
    __syncthreads();

    // --- phase 2: features + per-feature sums ---
    float fs[8] = {0.f, 0.f, 0.f, 0.f, 0.f, 0.f, 0.f, 0.f};
#pragma unroll
    for (int r = 0; r < 4; r++) {
        int j = t + r * 128;
        const float* xp = xg + base + j * 3;
        float a = xp[0], bb = xp[1], c = xp[2];
        float d  = a * a + bb * bb + c * c;
        float ri = rsqrtf(d);
        float n  = d * ri;
        float e1 = a * ri, e2 = bb * ri, e3 = c * ri;
        ftr[0 * 512 + j] = n;  ftr[1 * 512 + j] = e1;
        ftr[2 * 512 + j] = e2; ftr[3 * 512 + j] = e3;
        fs[0] += n; fs[1] += e1; fs[2] += e2; fs[3] += e3;
        float c0 = vxr[r] - vb0, c1 = vyr[r] - vb1, c2 = vzr[r] - vb2;
        d  = c0 * c0 + c1 * c1 + c2 * c2;
        ri = rsqrtf(d);
        n  = d * ri;
        e1 = c0 * ri; e2 = c1 * ri; e3 = c2 * ri;
        ftr[4 * 512 + j] = n;  ftr[5 * 512 + j] = e1;
        ftr[6 * 512 + j] = e2; ftr[7 * 512 + j] = e3;
        fs[4] += n; fs[5] += e1; fs[6] += e2; fs[7] += e3;
    }
#pragma unroll
    for (int off = 16; off; off >>= 1)
#pragma unroll
        for (int f = 0; f < 8; f++) fs[f] += __shfl_xor_sync(0xffffffffu, fs[f], off);
    if (lane == 0) {
#pragma unroll
        for (int f = 0; f < 8; f++) red[w * 8 + f] = fs[f];
    }
    __syncthreads();
    float fm[8];
#pragma unroll
    for (int f = 0; f < 8; f++)
        fm[f] = (red[f] + red[8 + f] + red[16 + f] + red[24 + f]) * (1.f / ND_);

    // --- per-i constant C ---
    float Nv = Ng[b * NT_ + i];
    const float* x0p = x0g + (b * NT_ + i) * 3;
    float p0 = x0p[0], p1 = x0p[1], p2 = x0p[2];
    float d0 = p0 * p0 + p1 * p1 + p2 * p2;
    float ri0 = rsqrtf(d0);
    float x0n = d0 * ri0;
    float u0 = p0 * ri0, u1 = p1 * ri0, u2 = p2 * ri0;
    float dv = vb0 * vb0 + vb1 * vb1 + vb2 * vb2;
    float riv = rsqrtf(dv);
    float vbn = dv * riv;
    float q0 = vb0 * riv, q1 = vb1 * riv, q2 = vb2 * riv;

    const float* wj = g_wj + b * 8 * HP_;
    const float* wc = g_wc + b * 10 * HP_;

    float C0, C1;
    {
        float c;
        c  = wc[9 * HP_ + h0];
        c += Nv  * wc[0 * HP_ + h0];
        c += x0n * wc[1 * HP_ + h0];
        c += u0 * wc[2 * HP_ + h0] + u1 * wc[3 * HP_ + h0] + u2 * wc[4 * HP_ + h0];
        c += vbn * wc[5 * HP_ + h0];
        c += q0 * wc[6 * HP_ + h0] + q1 * wc[7 * HP_ + h0] + q2 * wc[8 * HP_ + h0];
        C0 = c;
        c  = wc[9 * HP_ + h1i];
        c += Nv  * wc[0 * HP_ + h1i];
        c += x0n * wc[1 * HP_ + h1i];
        c += u0 * wc[2 * HP_ + h1i] + u1 * wc[3 * HP_ + h1i] + u2 * wc[4 * HP_ + h1i];
        c += vbn * wc[5 * HP_ + h1i];
        c += q0 * wc[6 * HP_ + h1i] + q1 * wc[7 * HP_ + h1i] + q2 * wc[8 * HP_ + h1i];
        C1 = c;
    }

    float w0s[8], w1s[8];
    u64t  w0p[8], w1p[8];
#pragma unroll
    for (int f = 0; f < 8; f++) {
        w0s[f] = wj[f * HP_ + h0];
        w1s[f] = wj[f * HP_ + h1i];
        w0p[f] = pack2(w0s[f], w0s[f]);
        w1p[f] = pack2(w1s[f], w1s[f]);
    }
    u64t C0p = pack2(C0, C0), C1p = pack2(C1, C1);

    // --- phase 3: hot loop (role-specialized) ---
    const u64t MASK = 0x7FFFFFFF7FFFFFFFULL;
    u64t acc0 = 0ull, acc1 = 0ull;
    if (role < 3) {
#pragma unroll 1
        for (int j4 = 0; j4 < 512; j4 += 4) {
            ulonglong2 qq[8];
#pragma unroll
            for (int f = 0; f < 8; f++)
                qq[f] = *(const ulonglong2*)(ftr + f * 512 + j4);
            u64t p;
            p = C0p;
#pragma unroll
            for (int f = 0; f < 8; f++) p = ffma2(qq[f].x, w0p[f], p);
            acc0 = add2(acc0, p & MASK);
            p = C0p;
#pragma unroll
            for (int f = 0; f < 8; f++) p = ffma2(qq[f].y, w0p[f], p);
            acc0 = add2(acc0, p & MASK);
            p = C1p;
#pragma unroll
            for (int f = 0; f < 8; f++) p = ffma2(qq[f].x, w1p[f], p);
            acc1 = add2(acc1, p & MASK);
            p = C1p;
#pragma unroll
            for (int f = 0; f < 8; f++) p = ffma2(qq[f].y, w1p[f], p);
            acc1 = add2(acc1, p & MASK);
        }
    } else {
#pragma unroll 1
        for (int j4 = 0; j4 < 512; j4 += 4) {
            ulonglong2 qq[8];
#pragma unroll
            for (int f = 0; f < 8; f++)
                qq[f] = *(const ulonglong2*)(ftr + f * 512 + j4);
            u64t p;
            p = C0p;
#pragma unroll
            for (int f = 0; f < 8; f++) p = ffma2(qq[f].x, w0p[f], p);
            acc0 = add2(acc0, p & MASK);
            p = C0p;
#pragma unroll
            for (int f = 0; f < 8; f++) p = ffma2(qq[f].y, w0p[f], p);
            acc0 = add2(acc0, p & MASK);
        }
    }

    float S0 = C0, S1 = C1;
#pragma unroll
    for (int f = 0; f < 8; f++) { S0 += fm[f] * w0s[f]; S1 += fm[f] * w1s[f]; }
    float2 e0 = unpack2(acc0), e1 = unpack2(acc1);
    float hm0 = 0.505f * S0 + (0.495f / ND_) * (e0.x + e0.y);
    float hm1 = 0.505f * S1 + (0.495f / ND_) * (e1.x + e1.y);
    float* hmp = g_hm + (b * NT_ + i) * NH_;
    hmp[h0] = hm0;
    if (h1i < NH_) hmp[h1i] = hm1;
}

// ---------------------------------------------------------------------------
// Tail v5 (R9/R13 verbatim): 512 CTAs x 4 rows, 256 threads, W prefetch.
// ---------------------------------------------------------------------------
#define KP_ 208

__global__ __launch_bounds__(256) void tail_kernel(
    const float* __restrict__ W1, const float* __restrict__ b1,
    const float* __restrict__ W2, const float* __restrict__ b2,
    float* __restrict__ out)
{
    __shared__ __align__(16) float hm_s[ROWS2_ * KP_];
    __shared__ __align__(16) float h2_s[ROWS2_ * KP_];

    int t = threadIdx.x;
    int row0 = blockIdx.x * ROWS2_;

    {
        float4* z0 = (float4*)hm_s;
        float4* z1 = (float4*)h2_s;
        for (int idx = t; idx < (ROWS2_ * KP_) / 4; idx += 256) {
            z0[idx] = make_float4(0.f, 0.f, 0.f, 0.f);
            z1[idx] = make_float4(0.f, 0.f, 0.f, 0.f);
        }
    }
    __syncthreads();
    {
        const float4* src = (const float4*)g_hm;
        float4* dst = (float4*)hm_s;
        for (int idx = t; idx < ROWS2_ * 49; idx += 256) {
            int r = idx / 49, c = idx - r * 49;
            dst[r * (KP_ / 4) + c] = src[(row0 + r) * 49 + c];
        }
    }
    __syncthreads();

    if (t < NH_) {
        float bv = b1[t];
        float a0 = bv, a1 = bv, a2 = bv, a3 = bv;
        float wcv[16];
#pragma unroll
        for (int u = 0; u < 16; u++) wcv[u] = W1[u * NH_ + t];
#pragma unroll 1
        for (int blk = 0; blk < 13; blk++) {
            int k  = blk * 16;
            int kn = k + 16;
            float wn[16];
#pragma unroll
            for (int u = 0; u < 16; u++)
                wn[u] = (kn + u < NH_) ? W1[(kn + u) * NH_ + t] : 0.f;
#pragma unroll
            for (int c4 = 0; c4 < 4; c4++) {
                int kk = k + c4 * 4;
                float4 h0 = *(const float4*)(hm_s + 0 * KP_ + kk);
                float4 h1 = *(const float4*)(hm_s + 1 * KP_ + kk);
                float4 h2 = *(const float4*)(hm_s + 2 * KP_ + kk);
                float4 h3 = *(const float4*)(hm_s + 3 * KP_ + kk);
                float w0 = wcv[c4 * 4 + 0], w1 = wcv[c4 * 4 + 1];
                float w2 = wcv[c4 * 4 + 2], w3 = wcv[c4 * 4 + 3];
                a0 = fmaf(h0.x, w0, a0); a0 = fmaf(h0.y, w1, a0);
                a0 = fmaf(h0.z, w2, a0); a0 = fmaf(h0.w, w3, a0);
                a1 = fmaf(h1.x, w0, a1); a1 = fmaf(h1.y, w1, a1);
                a1 = fmaf(h1.z, w2, a1); a1 = fmaf(h1.w, w3, a1);
                a2 = fmaf(h2.x, w0, a2); a2 = fmaf(h2.y, w1, a2);
                a2 = fmaf(h2.z, w2, a2); a2 = fmaf(h2.w, w3, a2);
                a3 = fmaf(h3.x, w0, a3); a3 = fmaf(h3.y, w1, a3);
                a3 = fmaf(h3.z, w2, a3); a3 = fmaf(h3.w, w3, a3);
            }
#pragma unroll
            for (int u = 0; u < 16; u++) wcv[u] = wn[u];
        }
        h2_s[0 * KP_ + t] = fmaxf(a0, 0.01f * a0);
        h2_s[1 * KP_ + t] = fmaxf(a1, 0.01f * a1);
        h2_s[2 * KP_ + t] = fmaxf(a2, 0.01f * a2);
        h2_s[3 * KP_ + t] = fmaxf(a3, 0.01f * a3);
    }
    __syncthreads();

    {
        int o  = t & (KL_ - 1);
        int r0 = (t >> 7) * 2;
        float bv = b2[o];
        float a0 = bv, a1 = bv;
        float wcv[16];
#pragma unroll
        for (int u = 0; u < 16; u++) wcv[u] = W2[u * KL_ + o];
#pragma unroll 1
        for (int blk = 0; blk < 13; blk++) {
            int k  = blk * 16;
            int kn = k + 16;
            float wn[16];
#pragma unroll
            for (int u = 0; u < 16; u++)
                wn[u] = (kn + u < NH_) ? W2[(kn + u) * KL_ + o] : 0.f;
#pragma unroll
            for (int c4 = 0; c4 < 4; c4++) {
                int kk = k + c4 * 4;
                float4 h0 = *(const float4*)(h2_s + (r0 + 0) * KP_ + kk);
                float4 h1 = *(const float4*)(h2_s + (r0 + 1) * KP_ + kk);
                float w0 = wcv[c4 * 4 + 0], w1 = wcv[c4 * 4 + 1];
                float w2 = wcv[c4 * 4 + 2], w3 = wcv[c4 * 4 + 3];
                a0 = fmaf(h0.x, w0, a0); a0 = fmaf(h0.y, w1, a0);
                a0 = fmaf(h0.z, w2, a0); a0 = fmaf(h0.w, w3, a0);
                a1 = fmaf(h1.x, w0, a1); a1 = fmaf(h1.y, w1, a1);
                a1 = fmaf(h1.z, w2, a1); a1 = fmaf(h1.w, w3, a1);
            }
#pragma unroll
            for (int u = 0; u < 16; u++) wcv[u] = wn[u];
        }
        out[(row0 + r0 + 0) * KL_ + o] = a0;
        out[(row0 + r0 + 1) * KL_ + o] = a1;
    }
}

// ---------------------------------------------------------------------------
extern "C" void kernel_launch(void* const* d_in, const int* in_sizes, int n_in,
                              void* d_out, int out_size) {
    const float* x0    = (const float*)d_in[0];
    const float* x     = (const float*)d_in[1];
    const float* N     = (const float*)d_in[2];
    const float* basis = (const float*)d_in[3];
    const float* v     = (const float*)d_in[4];
    const float* W0    = (const float*)d_in[5];
    const float* b0    = (const float*)d_in[6];
    const float* W1    = (const float*)d_in[7];
    const float* b1    = (const float*)d_in[8];
    const float* W2    = (const float*)d_in[9];
    const float* b2    = (const float*)d_in[10];

    precomp_kernel<<<B_, HP_>>>(W0, b0, basis);
    main_kernel<<<B_ * NT_, 128>>>(x0, x, N, v);
    tail_kernel<<<(B_ * NT_) / ROWS2_, 256>>>(W1, b1, W2, b2, (float*)d_out);
}

// round 15
// speedup vs baseline: 1.0740x; 1.0740x over previous
#include <cuda_runtime.h>

#define B_   2
#define NT_  1024
#define ND_  512
#define NH_  196
#define HP_  256      // padded hidden dim (zeros for h >= 196)
#define KL_  128
#define TROWS 8       // tail rows per CTA

// scratch (device globals: allocation-free)
__device__ float g_wj[B_ * 8 * HP_];
__device__ float g_wc[B_ * 10 * HP_];
__device__ float g_hm[B_ * NT_ * NH_];

typedef unsigned long long u64t;

__device__ __forceinline__ u64t pack2(float x, float y) {
    u64t r; asm("mov.b64 %0, {%1, %2};" : "=l"(r) : "f"(x), "f"(y)); return r;
}
__device__ __forceinline__ float2 unpack2(u64t v) {
    float2 r; asm("mov.b64 {%0, %1}, %2;" : "=f"(r.x), "=f"(r.y) : "l"(v)); return r;
}
__device__ __forceinline__ u64t ffma2(u64t a, u64t b, u64t c) {
    u64t d; asm("fma.rn.f32x2 %0, %1, %2, %3;" : "=l"(d) : "l"(a), "l"(b), "l"(c)); return d;
}
__device__ __forceinline__ u64t add2(u64t a, u64t b) {
    u64t d; asm("add.rn.f32x2 %0, %1, %2;" : "=l"(d) : "l"(a), "l"(b)); return d;
}

// ---------------------------------------------------------------------------
// Kernel 1: fold basis into W0 rows (tiny)  [R13 verbatim]
// ---------------------------------------------------------------------------
__global__ void precomp_kernel(const float* __restrict__ W0,
                               const float* __restrict__ b0,
                               const float* __restrict__ basis) {
    int b = blockIdx.x, h = threadIdx.x;
    float* wj = g_wj + b * 8 * HP_;
    float* wc = g_wc + b * 10 * HP_;
    if (h >= NH_) {
        for (int r = 0; r < 8;  r++) wj[r * HP_ + h] = 0.f;
        for (int r = 0; r < 10; r++) wc[r * HP_ + h] = 0.f;
        return;
    }
    const float* bs = basis + b * 6 * 3;
    wj[0 * HP_ + h] = W0[15 * NH_ + h];
    wj[4 * HP_ + h] = W0[22 * NH_ + h];
    wc[0 * HP_ + h] = W0[0 * NH_ + h];
    wc[1 * HP_ + h] = W0[1 * NH_ + h];
    wc[5 * HP_ + h] = W0[8 * NH_ + h];
    wc[9 * HP_ + h] = b0[h];
    for (int d = 0; d < 3; d++) {
        float m0x = 0.f, m0v = 0.f, m1 = 0.f, m2 = 0.f;
        for (int k = 0; k < 6; k++) {
            float bb = bs[k * 3 + d];
            m0x += bb * W0[(2  + k) * NH_ + h];
            m0v += bb * W0[(9  + k) * NH_ + h];
            m1  += bb * W0[(16 + k) * NH_ + h];
            m2  += bb * W0[(23 + k) * NH_ + h];
        }
        wj[(1 + d) * HP_ + h] = m1;
        wj[(5 + d) * HP_ + h] = m2;
        wc[(2 + d) * HP_ + h] = m0x;
        wc[(6 + d) * HP_ + h] = m0v;
    }
}

// ---------------------------------------------------------------------------
// Kernel 2 [R13 verbatim]: 128 threads, warps 0-2 heavy (2-h), warp 3 light.
// ---------------------------------------------------------------------------
__global__ __launch_bounds__(128) void main_kernel(
    const float* __restrict__ x0g, const float* __restrict__ xg,
    const float* __restrict__ Ng,  const float* __restrict__ vg) {
    __shared__ float4 ftr4[8 * 128];
    float* ftr = (float*)ftr4;
    __shared__ float red[32];

    int t = threadIdx.x;
    int blk = blockIdx.x;
    int b = blk >> 10, i = blk & (NT_ - 1);
    int lane = t & 31, w = t >> 5;
    int base = (b * NT_ + i) * ND_ * 3;

    // --- phase 1: vbulk ---
    float vxr[4], vyr[4], vzr[4];
    float s0 = 0.f, s1 = 0.f, s2 = 0.f;
#pragma unroll
    for (int r = 0; r < 4; r++) {
        int j = t + r * 128;
        const float* vp = vg + base + j * 3;
        float a = vp[0], bb = vp[1], c = vp[2];
        vxr[r] = a; vyr[r] = bb; vzr[r] = c;
        s0 += a; s1 += bb; s2 += c;
    }
#pragma unroll
    for (int off = 16; off; off >>= 1) {
        s0 += __shfl_xor_sync(0xffffffffu, s0, off);
        s1 += __shfl_xor_sync(0xffffffffu, s1, off);
        s2 += __shfl_xor_sync(0xffffffffu, s2, off);
    }
    if (lane == 0) { red[w * 8 + 0] = s0; red[w * 8 + 1] = s1; red[w * 8 + 2] = s2; }
    __syncthreads();
    float vb0 = (red[0] + red[8]  + red[16] + red[24]) * (1.f / ND_);
    float vb1 = (red[1] + red[9]  + red[17] + red[25]) * (1.f / ND_);
    float vb2 = (red[2] + red[10] + red[18] + red[26]) * (1.f / ND_);
    __syncthreads();

    // --- phase 2: features + per-feature sums ---
    float fs[8] = {0.f, 0.f, 0.f, 0.f, 0.f, 0.f, 0.f, 0.f};
#pragma unroll
    for (int r = 0; r < 4; r++) {
        int j = t + r * 128;
        const float* xp = xg + base + j * 3;
        float a = xp[0], bb = xp[1], c = xp[2];
        float d  = a * a + bb * bb + c * c;
        float ri = rsqrtf(d);
        float n  = d * ri;
        float e1 = a * ri, e2 = bb * ri, e3 = c * ri;
        ftr[0 * 512 + j] = n;  ftr[1 * 512 + j] = e1;
        ftr[2 * 512 + j] = e2; ftr[3 * 512 + j] = e3;
        fs[0] += n; fs[1] += e1; fs[2] += e2; fs[3] += e3;
        float c0 = vxr[r] - vb0, c1 = vyr[r] - vb1, c2 = vzr[r] - vb2;
        d  = c0 * c0 + c1 * c1 + c2 * c2;
        ri = rsqrtf(d);
        n  = d * ri;
        e1 = c0 * ri; e2 = c1 * ri; e3 = c2 * ri;
        ftr[4 * 512 + j] = n;  ftr[5 * 512 + j] = e1;
        ftr[6 * 512 + j] = e2; ftr[7 * 512 + j] = e3;
        fs[4] += n; fs[5] += e1; fs[6] += e2; fs[7] += e3;
    }
#pragma unroll
    for (int off = 16; off; off >>= 1)
#pragma unroll
        for (int f = 0; f < 8; f++) fs[f] += __shfl_xor_sync(0xffffffffu, fs[f], off);
    if (lane == 0) {
#pragma unroll
        for (int f = 0; f < 8; f++) red[w * 8 + f] = fs[f];
    }
    __syncthreads();
    float fm[8];
#pragma unroll
    for (int f = 0; f < 8; f++)
        fm[f] = (red[f] + red[8 + f] + red[16 + f] + red[24 + f]) * (1.f / ND_);

    // --- per-i constant C ---
    float Nv = Ng[b * NT_ + i];
    const float* x0p = x0g + (b * NT_ + i) * 3;
    float p0 = x0p[0], p1 = x0p[1], p2 = x0p[2];
    float d0 = p0 * p0 + p1 * p1 + p2 * p2;
    float ri0 = rsqrtf(d0);
    float x0n = d0 * ri0;
    float u0 = p0 * ri0, u1 = p1 * ri0, u2 = p2 * ri0;
    float dv = vb0 * vb0 + vb1 * vb1 + vb2 * vb2;
    float riv = rsqrtf(dv);
    float vbn = dv * riv;
    float q0 = vb0 * riv, q1 = vb1 * riv, q2 = vb2 * riv;

    const float* wj = g_wj + b * 8 * HP_;
    const float* wc = g_wc + b * 10 * HP_;
    int h0 = t, h1i = t + 128;

    float C0, C1;
    {
        float c;
        c  = wc[9 * HP_ + h0];
        c += Nv  * wc[0 * HP_ + h0];
        c += x0n * wc[1 * HP_ + h0];
        c += u0 * wc[2 * HP_ + h0] + u1 * wc[3 * HP_ + h0] + u2 * wc[4 * HP_ + h0];
        c += vbn * wc[5 * HP_ + h0];
        c += q0 * wc[6 * HP_ + h0] + q1 * wc[7 * HP_ + h0] + q2 * wc[8 * HP_ + h0];
        C0 = c;
        c  = wc[9 * HP_ + h1i];
        c += Nv  * wc[0 * HP_ + h1i];
        c += x0n * wc[1 * HP_ + h1i];
        c += u0 * wc[2 * HP_ + h1i] + u1 * wc[3 * HP_ + h1i] + u2 * wc[4 * HP_ + h1i];
        c += vbn * wc[5 * HP_ + h1i];
        c += q0 * wc[6 * HP_ + h1i] + q1 * wc[7 * HP_ + h1i] + q2 * wc[8 * HP_ + h1i];
        C1 = c;
    }

    float w0s[8], w1s[8];
    u64t  w0p[8], w1p[8];
#pragma unroll
    for (int f = 0; f < 8; f++) {
        w0s[f] = wj[f * HP_ + h0];
        w1s[f] = wj[f * HP_ + h1i];
        w0p[f] = pack2(w0s[f], w0s[f]);
        w1p[f] = pack2(w1s[f], w1s[f]);
    }
    u64t C0p = pack2(C0, C0), C1p = pack2(C1, C1);

    // --- phase 3: hot loop (warp-specialized) ---
    const u64t MASK = 0x7FFFFFFF7FFFFFFFULL;
    u64t acc0 = 0ull, acc1 = 0ull;
    if (w < 3) {
#pragma unroll 1
        for (int j4 = 0; j4 < 512; j4 += 4) {
            ulonglong2 qq[8];
#pragma unroll
            for (int f = 0; f < 8; f++)
                qq[f] = *(const ulonglong2*)(ftr + f * 512 + j4);
            u64t p;
            p = C0p;
#pragma unroll
            for (int f = 0; f < 8; f++) p = ffma2(qq[f].x, w0p[f], p);
            acc0 = add2(acc0, p & MASK);
            p = C0p;
#pragma unroll
            for (int f = 0; f < 8; f++) p = ffma2(qq[f].y, w0p[f], p);
            acc0 = add2(acc0, p & MASK);
            p = C1p;
#pragma unroll
            for (int f = 0; f < 8; f++) p = ffma2(qq[f].x, w1p[f], p);
            acc1 = add2(acc1, p & MASK);
            p = C1p;
#pragma unroll
            for (int f = 0; f < 8; f++) p = ffma2(qq[f].y, w1p[f], p);
            acc1 = add2(acc1, p & MASK);
        }
    } else {
#pragma unroll 1
        for (int j4 = 0; j4 < 512; j4 += 4) {
            ulonglong2 qq[8];
#pragma unroll
            for (int f = 0; f < 8; f++)
                qq[f] = *(const ulonglong2*)(ftr + f * 512 + j4);
            u64t p;
            p = C0p;
#pragma unroll
            for (int f = 0; f < 8; f++) p = ffma2(qq[f].x, w0p[f], p);
            acc0 = add2(acc0, p & MASK);
            p = C0p;
#pragma unroll
            for (int f = 0; f < 8; f++) p = ffma2(qq[f].y, w0p[f], p);
            acc0 = add2(acc0, p & MASK);
        }
    }

    float S0 = C0, S1 = C1;
#pragma unroll
    for (int f = 0; f < 8; f++) { S0 += fm[f] * w0s[f]; S1 += fm[f] * w1s[f]; }
    float2 e0 = unpack2(acc0), e1 = unpack2(acc1);
    float hm0 = 0.505f * S0 + (0.495f / ND_) * (e0.x + e0.y);
    float hm1 = 0.505f * S1 + (0.495f / ND_) * (e1.x + e1.y);
    float* hmp = g_hm + (b * NT_ + i) * NH_;
    hmp[h0] = hm0;
    if (h1i < NH_) hmp[h1i] = hm1;
}

// ---------------------------------------------------------------------------
// Tail v7: grid 256 x 8 rows, 512 threads (16 warps).
// Layer 1 k-split: threads 0..391 = (k-half, h); kh=0 covers k[0,96) (6 blocks
// of 16), kh=1 covers k[96,208) (7 blocks, zero-padded beyond 195). Partials
// combined in smem. Layer 2: 4 row-pairs x 128 outputs over all 512 threads.
// Halves W traffic vs grid-512 and doubles latency-hiding warps.
// ---------------------------------------------------------------------------
#define KP_ 208

__global__ __launch_bounds__(512) void tail_kernel(
    const float* __restrict__ W1, const float* __restrict__ b1,
    const float* __restrict__ W2, const float* __restrict__ b2,
    float* __restrict__ out)
{
    __shared__ __align__(16) float hm_s[TROWS * KP_];        // 6.5 KB
    __shared__ __align__(16) float h2_s[TROWS * KP_];        // 6.5 KB
    __shared__ __align__(16) float part_s[2 * TROWS * NH_];  // 12.25 KB

    int t = threadIdx.x;
    int row0 = blockIdx.x * TROWS;

    // zero pads (k >= 196 region must be 0 in both row buffers)
    for (int idx = t; idx < (TROWS * KP_) / 4; idx += 512) {
        ((float4*)hm_s)[idx] = make_float4(0.f, 0.f, 0.f, 0.f);
        ((float4*)h2_s)[idx] = make_float4(0.f, 0.f, 0.f, 0.f);
    }
    __syncthreads();
    // stage hm rows (49 float4 per row; row base 196*4B is 16B-aligned)
    {
        const float4* src = (const float4*)g_hm;
        float4* dst = (float4*)hm_s;
        for (int idx = t; idx < TROWS * 49; idx += 512) {
            int r = idx / 49, c = idx - r * 49;
            dst[r * (KP_ / 4) + c] = src[(row0 + r) * 49 + c];
        }
    }
    __syncthreads();

    // ---- layer 1: (kh, h) threads; 8-row partials over half the k range ----
    if (t < 2 * NH_) {
        int kh = (t >= NH_) ? 1 : 0;
        int h  = t - kh * NH_;
        float a0 = 0.f, a1 = 0.f, a2 = 0.f, a3 = 0.f;
        float a4 = 0.f, a5 = 0.f, a6 = 0.f, a7 = 0.f;
        int kstart = kh ? 96 : 0;
        int nblk   = kh ? 7 : 6;
#pragma unroll 1
        for (int blk = 0; blk < nblk; blk++) {
            int k = kstart + blk * 16;
            float wv[16];
#pragma unroll
            for (int u = 0; u < 16; u++)
                wv[u] = (k + u < NH_) ? W1[(k + u) * NH_ + h] : 0.f;
#pragma unroll
            for (int c4 = 0; c4 < 4; c4++) {
                int kk = k + c4 * 4;
                float4 h0 = *(const float4*)(hm_s + 0 * KP_ + kk);
                float4 h1 = *(const float4*)(hm_s + 1 * KP_ + kk);
                float4 h2 = *(const float4*)(hm_s + 2 * KP_ + kk);
                float4 h3 = *(const float4*)(hm_s + 3 * KP_ + kk);
                float4 h4 = *(const float4*)(hm_s + 4 * KP_ + kk);
                float4 h5 = *(const float4*)(hm_s + 5 * KP_ + kk);
                float4 h6 = *(const float4*)(hm_s + 6 * KP_ + kk);
                float4 h7 = *(const float4*)(hm_s + 7 * KP_ + kk);
                float w0 = wv[c4 * 4 + 0], w1 = wv[c4 * 4 + 1];
                float w2 = wv[c4 * 4 + 2], w3 = wv[c4 * 4 + 3];
                a0 = fmaf(h0.x, w0, a0); a0 = fmaf(h0.y, w1, a0);
                a0 = fmaf(h0.z, w2, a0); a0 = fmaf(h0.w, w3, a0);
                a1 = fmaf(h1.x, w0, a1); a1 = fmaf(h1.y, w1, a1);
                a1 = fmaf(h1.z, w2, a1); a1 = fmaf(h1.w, w3, a1);
                a2 = fmaf(h2.x, w0, a2); a2 = fmaf(h2.y, w1, a2);
                a2 = fmaf(h2.z, w2, a2); a2 = fmaf(h2.w, w3, a2);
                a3 = fmaf(h3.x, w0, a3); a3 = fmaf(h3.y, w1, a3);
                a3 = fmaf(h3.z, w2, a3); a3 = fmaf(h3.w, w3, a3);
                a4 = fmaf(h4.x, w0, a4); a4 = fmaf(h4.y, w1, a4);
                a4 = fmaf(h4.z, w2, a4); a4 = fmaf(h4.w, w3, a4);
                a5 = fmaf(h5.x, w0, a5); a5 = fmaf(h5.y, w1, a5);
                a5 = fmaf(h5.z, w2, a5); a5 = fmaf(h5.w, w3, a5);
                a6 = fmaf(h6.x, w0, a6); a6 = fmaf(h6.y, w1, a6);
                a6 = fmaf(h6.z, w2, a6); a6 = fmaf(h6.w, w3, a6);
                a7 = fmaf(h7.x, w0, a7); a7 = fmaf(h7.y, w1, a7);
                a7 = fmaf(h7.z, w2, a7); a7 = fmaf(h7.w, w3, a7);
            }
        }
        float* pp = part_s + kh * TROWS * NH_ + h;
        pp[0 * NH_] = a0; pp[1 * NH_] = a1; pp[2 * NH_] = a2; pp[3 * NH_] = a3;
        pp[4 * NH_] = a4; pp[5 * NH_] = a5; pp[6 * NH_] = a6; pp[7 * NH_] = a7;
    }
    __syncthreads();

    // ---- combine halves + bias + leaky -> h2_s ----
    if (t < NH_) {
        float bv = b1[t];
#pragma unroll
        for (int r = 0; r < TROWS; r++) {
            float z = part_s[r * NH_ + t] + part_s[TROWS * NH_ + r * NH_ + t] + bv;
            h2_s[r * KP_ + t] = fmaxf(z, 0.01f * z);
        }
    }
    __syncthreads();

    // ---- layer 2: o = t&127, row pair rp = t>>7 (rows 2rp, 2rp+1) ----
    {
        int o  = t & (KL_ - 1);
        int r0 = (t >> 7) * 2;
        float bv = b2[o];
        float c0 = bv, c1 = bv;
#pragma unroll 1
        for (int blk = 0; blk < 13; blk++) {
            int k = blk * 16;
            float wv[16];
#pragma unroll
            for (int u = 0; u < 16; u++)
                wv[u] = (k + u < NH_) ? W2[(k + u) * KL_ + o] : 0.f;
#pragma unroll
            for (int c4 = 0; c4 < 4; c4++) {
                int kk = k + c4 * 4;
                float4 h0 = *(const float4*)(h2_s + (r0 + 0) * KP_ + kk);
                float4 h1 = *(const float4*)(h2_s + (r0 + 1) * KP_ + kk);
                float w0 = wv[c4 * 4 + 0], w1 = wv[c4 * 4 + 1];
                float w2 = wv[c4 * 4 + 2], w3 = wv[c4 * 4 + 3];
                c0 = fmaf(h0.x, w0, c0); c0 = fmaf(h0.y, w1, c0);
                c0 = fmaf(h0.z, w2, c0); c0 = fmaf(h0.w, w3, c0);
                c1 = fmaf(h1.x, w0, c1); c1 = fmaf(h1.y, w1, c1);
                c1 = fmaf(h1.z, w2, c1); c1 = fmaf(h1.w, w3, c1);
            }
        }
        out[(row0 + r0 + 0) * KL_ + o] = c0;
        out[(row0 + r0 + 1) * KL_ + o] = c1;
    }
}

// ---------------------------------------------------------------------------
extern "C" void kernel_launch(void* const* d_in, const int* in_sizes, int n_in,
                              void* d_out, int out_size) {
    const float* x0    = (const float*)d_in[0];
    const float* x     = (const float*)d_in[1];
    const float* N     = (const float*)d_in[2];
    const float* basis = (const float*)d_in[3];
    const float* v     = (const float*)d_in[4];
    const float* W0    = (const float*)d_in[5];
    const float* b0    = (const float*)d_in[6];
    const float* W1    = (const float*)d_in[7];
    const float* b1    = (const float*)d_in[8];
    const float* W2    = (const float*)d_in[9];
    const float* b2    = (const float*)d_in[10];

    precomp_kernel<<<B_, HP_>>>(W0, b0, basis);
    main_kernel<<<B_ * NT_, 128>>>(x0, x, N, v);
    tail_kernel<<<(B_ * NT_) / TROWS, 512>>>(W1, b1, W2, b2, (float*)d_out);
}